// round 11
// baseline (speedup 1.0000x reference)
#include <cuda_runtime.h>
#include <cuda_bf16.h>
#include <math.h>
#include <stdint.h>

#define BDIM 512
#define NTOK 256
#define HNUM 8
#define HD   32

// ---------------- scratch (device globals; referenced ONLY in device code) --
__device__ __align__(256) __nv_bfloat16 g_xh[BDIM*NTOK*256];   // x hi (67MB)
__device__ __align__(256) __nv_bfloat16 g_xl[BDIM*NTOK*256];   // x lo
__device__ __align__(256) __nv_bfloat16 g_qh[BDIM*HNUM*NTOK*HD];
__device__ __align__(256) __nv_bfloat16 g_kh[BDIM*HNUM*NTOK*HD];
__device__ __align__(256) __nv_bfloat16 g_vh[BDIM*HNUM*NTOK*HD];
__device__ __align__(256) __nv_bfloat16 g_vl[BDIM*HNUM*NTOK*HD];
__device__ __align__(256) __nv_bfloat16 g_ath[BDIM*NTOK*256];  // attn out hi
__device__ __align__(256) __nv_bfloat16 g_atl[BDIM*NTOK*256];  // attn out lo
__device__ __align__(256) __nv_bfloat16 g_wqkv_hi[768*256];
__device__ __align__(256) __nv_bfloat16 g_wqkv_lo[768*256];
__device__ __align__(256) __nv_bfloat16 g_wp_hi[256*256];
__device__ __align__(256) __nv_bfloat16 g_wp_lo[256*256];
__device__ __align__(256) __nv_bfloat16 g_bqh[HNUM*NTOK*HD];
__device__ __align__(256) __nv_bfloat16 g_bql[HNUM*NTOK*HD];
__device__ __align__(256) __nv_bfloat16 g_bkh[HNUM*NTOK*HD];
__device__ __align__(256) __nv_bfloat16 g_bkl[HNUM*NTOK*HD];

// ---------------- helpers ----------------------------------------------------
__device__ __forceinline__ uint32_t smem_u32(const void* p) {
    uint32_t a;
    asm("{ .reg .u64 t; cvta.to.shared.u64 t, %1; cvt.u32.u64 %0, t; }" : "=r"(a) : "l"(p));
    return a;
}
__device__ __forceinline__ uint32_t packbf(float x, float y) {
    uint32_t r;
    asm("cvt.rn.bf16x2.f32 %0, %1, %2;" : "=r"(r) : "f"(y), "f"(x));
    return r;
}
__device__ __forceinline__ void split2(float x, float y, uint32_t& hi, uint32_t& lo) {
    hi = packbf(x, y);
    float hx = __uint_as_float(hi << 16);
    float hy = __uint_as_float(hi & 0xffff0000u);
    lo = packbf(x - hx, y - hy);
}
__device__ __forceinline__ void ldsm4(uint32_t (&r)[4], uint32_t a) {
    asm volatile("ldmatrix.sync.aligned.m8n8.x4.shared.b16 {%0,%1,%2,%3}, [%4];"
        : "=r"(r[0]), "=r"(r[1]), "=r"(r[2]), "=r"(r[3]) : "r"(a));
}
__device__ __forceinline__ void ldsm4t(uint32_t (&r)[4], uint32_t a) {
    asm volatile("ldmatrix.sync.aligned.m8n8.x4.trans.shared.b16 {%0,%1,%2,%3}, [%4];"
        : "=r"(r[0]), "=r"(r[1]), "=r"(r[2]), "=r"(r[3]) : "r"(a));
}
__device__ __forceinline__ void mma16816(float4& c, const uint32_t (&a)[4],
                                         uint32_t b0, uint32_t b1) {
    asm volatile("mma.sync.aligned.m16n8k16.row.col.f32.bf16.bf16.f32 "
        "{%0,%1,%2,%3}, {%4,%5,%6,%7}, {%8,%9}, {%0,%1,%2,%3};"
        : "+f"(c.x), "+f"(c.y), "+f"(c.z), "+f"(c.w)
        : "r"(a[0]), "r"(a[1]), "r"(a[2]), "r"(a[3]), "r"(b0), "r"(b1));
}
__device__ __forceinline__ void cpasync16(uint32_t dst, const void* src) {
    asm volatile("cp.async.cg.shared.global [%0], [%1], 16;" :: "r"(dst), "l"(src));
}
#define CP_COMMIT() asm volatile("cp.async.commit_group;" ::: "memory")
#define CP_WAIT(n)  asm volatile("cp.async.wait_group %0;" :: "n"(n) : "memory")

// ---------------- kernel 0a: x -> bf16 hi/lo --------------------------------
__global__ __launch_bounds__(256) void prep_x_kernel(const float* __restrict__ x) {
    size_t idx = ((size_t)blockIdx.x * 256 + threadIdx.x) * 4;
    float4 v = *(const float4*)(x + idx);
    uint32_t h0, l0, h1, l1;
    split2(v.x, v.y, h0, l0);
    split2(v.z, v.w, h1, l1);
    *(uint2*)(g_xh + idx) = make_uint2(h0, h1);
    *(uint2*)(g_xl + idx) = make_uint2(l0, l1);
}

// ---------------- kernel 0b: weight transpose + bf16 split ------------------
__global__ __launch_bounds__(256) void prep_w_kernel(
    const float* __restrict__ qkv_w, const float* __restrict__ proj_w) {
    int idx = blockIdx.x * 256 + threadIdx.x;
    if (idx < 196608) {
        int n = idx >> 8, k = idx & 255;
        float v = qkv_w[k * 768 + n];
        __nv_bfloat16 h = __float2bfloat16(v);
        g_wqkv_hi[idx] = h;
        g_wqkv_lo[idx] = __float2bfloat16(v - __bfloat162float(h));
    } else {
        int j = idx - 196608;
        int n = j >> 8, k = j & 255;
        float v = proj_w[k * 256 + n];
        __nv_bfloat16 h = __float2bfloat16(v);
        g_wp_hi[j] = h;
        g_wp_lo[j] = __float2bfloat16(v - __bfloat162float(h));
    }
}

// ---------------- kernel 1: MLP -> bq, bk (bf16 hi/lo) ----------------------
__global__ __launch_bounds__(128) void bias_mlp_kernel(
    const float* __restrict__ m1w, const float* __restrict__ m1b,
    const float* __restrict__ m2w, const float* __restrict__ bs) {
    __shared__ float hf[128];
    const int n = blockIdx.x;
    const int t = threadIdx.x;
    const float invden = 1.0f / log1pf(15.0f);
    const float cy = log1pf((float)(n >> 4)) * invden;
    const float cx = log1pf((float)(n & 15)) * invden;
    {
        float z = cy * m1w[t] + cx * m1w[128 + t] + m1b[t];
        hf[t] = 0.5f * z * (1.0f + erff(z * 0.70710678118654752f));
    }
    __syncthreads();
    const float bscale = bs[0];
    for (int c = t; c < 512; c += 128) {
        float acc = 0.0f;
        #pragma unroll 8
        for (int j = 0; j < 128; j++) acc += hf[j] * m2w[j * 512 + c];
        float sig = 1.0f / (1.0f + __expf(-acc));
        int h = c >> 6, s = (c >> 5) & 1, r = c & 31;
        float v = (s == 0) ? bscale * sig : sig;
        __nv_bfloat16 vh = __float2bfloat16(v);
        __nv_bfloat16 vl = __float2bfloat16(v - __bfloat162float(vh));
        int idx = (h * NTOK + n) * 32 + r;
        if (s == 0) { g_bqh[idx] = vh; g_bql[idx] = vl; }
        else        { g_bkh[idx] = vh; g_bkl[idx] = vl; }
    }
}

// ---------------- GEMM: pre-split bf16 A (global frags) + B smem ------------
// smem per buffer: hi[128][40bf16]=10240 + lo=10240 -> 20480; x2 = 40960
#define GEMM_BUF_BYTES 20480
#define GEMM_SMEM_BYTES (2 * GEMM_BUF_BYTES)

template <bool QKV>
__global__ __launch_bounds__(256, 2) void gemm_mma_kernel(
    const float* __restrict__ bias, const float* __restrict__ ls,
    float* __restrict__ outp) {
    extern __shared__ char sm[];
    const uint32_t sb = smem_u32(sm);
    const int t = threadIdx.x, w = t >> 5, lane = t & 31;
    const int m0 = blockIdx.y * 128 + w * 16;
    const int c0 = blockIdx.x * 128;
    const int r = lane >> 2, cc = (lane & 3) * 2;
    const int lrow = (lane & 7) + ((lane >> 4) << 3);
    const int lcol2 = (((lane >> 3) & 1) << 3) * 2;

    const __nv_bfloat16* Ah = QKV ? g_xh : g_ath;
    const __nv_bfloat16* Al = QKV ? g_xl : g_atl;
    const __nv_bfloat16* Bh = QKV ? g_wqkv_hi : g_wp_hi;
    const __nv_bfloat16* Bl = QKV ? g_wqkv_lo : g_wp_lo;
    const bool need_lo = QKV ? (blockIdx.x >= 4) : true;

    float4 acc[16];
    #pragma unroll
    for (int i = 0; i < 16; i++) acc[i] = make_float4(0.f, 0.f, 0.f, 0.f);

    const __nv_bfloat16* ah0 = Ah + (size_t)(m0 + r) * 256;
    const __nv_bfloat16* ah8 = ah0 + 8 * 256;
    const __nv_bfloat16* al0 = Al + (size_t)(m0 + r) * 256;
    const __nv_bfloat16* al8 = al0 + 8 * 256;

    const int srow = t >> 1;
    const int half = t & 1;
    const __nv_bfloat16* bhsrc = Bh + (size_t)(c0 + srow) * 256 + half * 16;
    const __nv_bfloat16* blsrc = Bl + (size_t)(c0 + srow) * 256 + half * 16;
    const uint32_t sdst = sb + srow * 80 + half * 32;

    cpasync16(sdst, bhsrc);
    cpasync16(sdst + 16, bhsrc + 8);
    if (need_lo) {
        cpasync16(sdst + 10240, blsrc);
        cpasync16(sdst + 10240 + 16, blsrc + 8);
    }
    CP_COMMIT();

    #pragma unroll
    for (int kc = 0; kc < 8; kc++) {
        if (kc < 7) {
            uint32_t dst = sdst + ((kc + 1) & 1) * GEMM_BUF_BYTES;
            const __nv_bfloat16* srch = bhsrc + (kc + 1) * 32;
            cpasync16(dst, srch);
            cpasync16(dst + 16, srch + 8);
            if (need_lo) {
                const __nv_bfloat16* srcl = blsrc + (kc + 1) * 32;
                cpasync16(dst + 10240, srcl);
                cpasync16(dst + 10240 + 16, srcl + 8);
            }
            CP_COMMIT();
        }
        // A fragments: direct uint32 loads from pre-split bf16 (no ALU chain)
        uint32_t ah[2][4], al[2][4];
        #pragma unroll
        for (int kk = 0; kk < 2; kk++) {
            int o = kc * 32 + kk * 16 + cc;
            ah[kk][0] = *(const uint32_t*)(ah0 + o);
            ah[kk][1] = *(const uint32_t*)(ah8 + o);
            ah[kk][2] = *(const uint32_t*)(ah0 + o + 8);
            ah[kk][3] = *(const uint32_t*)(ah8 + o + 8);
            al[kk][0] = *(const uint32_t*)(al0 + o);
            al[kk][1] = *(const uint32_t*)(al8 + o);
            al[kk][2] = *(const uint32_t*)(al0 + o + 8);
            al[kk][3] = *(const uint32_t*)(al8 + o + 8);
        }
        if (kc < 7) CP_WAIT(1); else CP_WAIT(0);
        __syncthreads();

        const uint32_t bufb = sb + (kc & 1) * GEMM_BUF_BYTES;
        #pragma unroll
        for (int n16 = 0; n16 < 8; n16++) {
            uint32_t off = (uint32_t)((n16 * 16 + lrow) * 80) + lcol2;
            uint32_t rh0[4], rh1[4];
            ldsm4(rh0, bufb + off);
            ldsm4(rh1, bufb + off + 32);
            float4& cA = acc[2 * n16];
            float4& cB = acc[2 * n16 + 1];
            mma16816(cA, ah[0], rh0[0], rh0[1]); mma16816(cA, ah[1], rh1[0], rh1[1]);
            mma16816(cA, al[0], rh0[0], rh0[1]); mma16816(cA, al[1], rh1[0], rh1[1]);
            mma16816(cB, ah[0], rh0[2], rh0[3]); mma16816(cB, ah[1], rh1[2], rh1[3]);
            mma16816(cB, al[0], rh0[2], rh0[3]); mma16816(cB, al[1], rh1[2], rh1[3]);
            if (need_lo) {
                uint32_t rl0[4], rl1[4];
                ldsm4(rl0, bufb + 10240 + off);
                ldsm4(rl1, bufb + 10240 + off + 32);
                mma16816(cA, ah[0], rl0[0], rl0[1]); mma16816(cA, ah[1], rl1[0], rl1[1]);
                mma16816(cB, ah[0], rl0[2], rl0[3]); mma16816(cB, ah[1], rl1[2], rl1[3]);
            }
        }
        __syncthreads();
    }

    const int mrow0 = m0 + r;
    if (QKV) {
        const int s = blockIdx.x >> 1;
        __nv_bfloat16* dh = (s == 0) ? g_qh : (s == 1 ? g_kh : g_vh);
        const int bidx = mrow0 >> 8, n0r = mrow0 & 255, n1r = n0r + 8;
        #pragma unroll
        for (int ti = 0; ti < 16; ti++) {
            int c = c0 + ti * 8 + cc;
            float2 bb = *(const float2*)(bias + c);
            int rem = c & 255;
            int h = rem >> 5, d = rem & 31;
            float scv = (s == 0) ? __ldg(ls + h) : 1.0f;
            float v00 = (acc[ti].x + bb.x) * scv, v01 = (acc[ti].y + bb.y) * scv;
            float v10 = (acc[ti].z + bb.x) * scv, v11 = (acc[ti].w + bb.y) * scv;
            size_t i0 = ((size_t)(bidx * 8 + h) * 256 + n0r) * 32 + d;
            size_t i1 = ((size_t)(bidx * 8 + h) * 256 + n1r) * 32 + d;
            if (s == 2) {
                uint32_t hi, lo;
                split2(v00, v01, hi, lo);
                *(uint32_t*)&dh[i0] = hi; *(uint32_t*)&g_vl[i0] = lo;
                split2(v10, v11, hi, lo);
                *(uint32_t*)&dh[i1] = hi; *(uint32_t*)&g_vl[i1] = lo;
            } else {
                *(uint32_t*)&dh[i0] = packbf(v00, v01);
                *(uint32_t*)&dh[i1] = packbf(v10, v11);
            }
        }
    } else {
        #pragma unroll
        for (int ti = 0; ti < 16; ti++) {
            int c = c0 + ti * 8 + cc;
            float2 bb = *(const float2*)(bias + c);
            *(float2*)(outp + (size_t)mrow0 * 256 + c) =
                make_float2(acc[ti].x + bb.x, acc[ti].y + bb.y);
            *(float2*)(outp + (size_t)(mrow0 + 8) * 256 + c) =
                make_float2(acc[ti].z + bb.x, acc[ti].w + bb.y);
        }
    }
}

// ---------------- attention: q hi-only, K hi-only, V hi+lo, bk 3-term -------
#define AS_KHI   0
#define AS_BKH   20480
#define AS_BKL   40960
#define AS_VHI   61440
#define AS_VLO   81920
#define AS_VMEAN 102400
#define AS_RED   102528
#define ATTN_SMEM_BYTES (102528 + 1024 + 512)

__global__ __launch_bounds__(256) void attn_mma_kernel(const float* __restrict__ vrs) {
    extern __shared__ char sm[];
    const uint32_t sb = smem_u32(sm);
    const int bh = blockIdx.x;
    const int b = bh >> 3, h = bh & 7;
    const int t = threadIdx.x, w = t >> 5, lane = t & 31;
    const int r = lane >> 2, cc = (lane & 3) * 2;
    const int lrow = (lane & 7) + ((lane >> 4) << 3);
    const int lcol2 = (((lane >> 3) & 1) << 3) * 2;
    const int lrowT = lane & 15;
    const int lcolT2 = ((lane >> 4) << 3) * 2;

    {
        size_t gk = (size_t)bh * 8192 + (size_t)t * 32;
        size_t gb = (size_t)h * 8192 + (size_t)t * 32;
        #pragma unroll
        for (int u = 0; u < 4; u++) {
            *(uint4*)(sm + AS_KHI + t * 80 + u * 16) = *(const uint4*)(g_kh + gk + u * 8);
            *(uint4*)(sm + AS_VHI + t * 80 + u * 16) = *(const uint4*)(g_vh + gk + u * 8);
            *(uint4*)(sm + AS_VLO + t * 80 + u * 16) = *(const uint4*)(g_vl + gk + u * 8);
            *(uint4*)(sm + AS_BKH + t * 80 + u * 16) = *(const uint4*)(g_bkh + gb + u * 8);
            *(uint4*)(sm + AS_BKL + t * 80 + u * 16) = *(const uint4*)(g_bkl + gb + u * 8);
        }
    }
    __syncthreads();

    {
        int d = t & 31, grp = t >> 5;
        float s = 0.0f;
        for (int n = grp * 32; n < grp * 32 + 32; n++) {
            uint16_t hv = *(const uint16_t*)(sm + AS_VHI + n * 80 + d * 2);
            uint16_t lv = *(const uint16_t*)(sm + AS_VLO + n * 80 + d * 2);
            s += __uint_as_float(((uint32_t)hv) << 16) + __uint_as_float(((uint32_t)lv) << 16);
        }
        ((float*)(sm + AS_RED))[grp * 32 + d] = s;
    }
    __syncthreads();
    if (t < 32) {
        float s = 0.0f;
        #pragma unroll
        for (int g = 0; g < 8; g++) s += ((float*)(sm + AS_RED))[g * 32 + t];
        ((float*)(sm + AS_VMEAN))[t] = s * (1.0f / 256.0f) * __ldg(vrs + h);
    }
    __syncthreads();

    for (int pass = 0; pass < 2; pass++) {
        const int tok0 = pass * 128 + w * 16 + r;
        uint32_t aqh[2][4], abh[2][4], abl[2][4];
        {
            size_t q0 = (size_t)bh * 8192 + (size_t)tok0 * 32;
            size_t b0 = (size_t)h * 8192 + (size_t)tok0 * 32;
            #pragma unroll
            for (int kk = 0; kk < 2; kk++) {
                int o = kk * 16 + cc;
                aqh[kk][0] = *(const uint32_t*)(g_qh + q0 + o);
                aqh[kk][1] = *(const uint32_t*)(g_qh + q0 + 256 + o);
                aqh[kk][2] = *(const uint32_t*)(g_qh + q0 + o + 8);
                aqh[kk][3] = *(const uint32_t*)(g_qh + q0 + 256 + o + 8);
                abh[kk][0] = *(const uint32_t*)(g_bqh + b0 + o);
                abh[kk][1] = *(const uint32_t*)(g_bqh + b0 + 256 + o);
                abh[kk][2] = *(const uint32_t*)(g_bqh + b0 + o + 8);
                abh[kk][3] = *(const uint32_t*)(g_bqh + b0 + 256 + o + 8);
                abl[kk][0] = *(const uint32_t*)(g_bql + b0 + o);
                abl[kk][1] = *(const uint32_t*)(g_bql + b0 + 256 + o);
                abl[kk][2] = *(const uint32_t*)(g_bql + b0 + o + 8);
                abl[kk][3] = *(const uint32_t*)(g_bql + b0 + 256 + o + 8);
            }
        }

        float4 sc[32];
        #pragma unroll
        for (int i = 0; i < 32; i++) sc[i] = make_float4(0.f, 0.f, 0.f, 0.f);
        #pragma unroll
        for (int n16 = 0; n16 < 16; n16++) {
            uint32_t off = (uint32_t)((n16 * 16 + lrow) * 80) + lcol2;
            uint32_t kh0[4], kh1[4];
            uint32_t bh0[4], bh1[4], bl0[4], bl1[4];
            ldsm4(kh0, sb + AS_KHI + off); ldsm4(kh1, sb + AS_KHI + off + 32);
            ldsm4(bh0, sb + AS_BKH + off); ldsm4(bh1, sb + AS_BKH + off + 32);
            ldsm4(bl0, sb + AS_BKL + off); ldsm4(bl1, sb + AS_BKL + off + 32);
            float4& cA = sc[2 * n16];
            float4& cB = sc[2 * n16 + 1];
            mma16816(cA, aqh[0], kh0[0], kh0[1]); mma16816(cA, aqh[1], kh1[0], kh1[1]);
            mma16816(cA, abh[0], bh0[0], bh0[1]); mma16816(cA, abh[1], bh1[0], bh1[1]);
            mma16816(cA, abl[0], bh0[0], bh0[1]); mma16816(cA, abl[1], bh1[0], bh1[1]);
            mma16816(cA, abh[0], bl0[0], bl0[1]); mma16816(cA, abh[1], bl1[0], bl1[1]);
            mma16816(cB, aqh[0], kh0[2], kh0[3]); mma16816(cB, aqh[1], kh1[2], kh1[3]);
            mma16816(cB, abh[0], bh0[2], bh0[3]); mma16816(cB, abh[1], bh1[2], bh1[3]);
            mma16816(cB, abl[0], bh0[2], bh0[3]); mma16816(cB, abl[1], bh1[2], bh1[3]);
            mma16816(cB, abh[0], bl0[2], bl0[3]); mma16816(cB, abh[1], bl1[2], bl1[3]);
        }

        float m0 = -1e30f, m1 = -1e30f;
        #pragma unroll
        for (int i = 0; i < 32; i++) {
            m0 = fmaxf(m0, fmaxf(sc[i].x, sc[i].y));
            m1 = fmaxf(m1, fmaxf(sc[i].z, sc[i].w));
        }
        m0 = fmaxf(m0, __shfl_xor_sync(0xffffffffu, m0, 1));
        m0 = fmaxf(m0, __shfl_xor_sync(0xffffffffu, m0, 2));
        m1 = fmaxf(m1, __shfl_xor_sync(0xffffffffu, m1, 1));
        m1 = fmaxf(m1, __shfl_xor_sync(0xffffffffu, m1, 2));
        float s0 = 0.f, s1 = 0.f;
        #pragma unroll
        for (int i = 0; i < 32; i++) {
            sc[i].x = __expf(sc[i].x - m0); sc[i].y = __expf(sc[i].y - m0);
            sc[i].z = __expf(sc[i].z - m1); sc[i].w = __expf(sc[i].w - m1);
            s0 += sc[i].x + sc[i].y; s1 += sc[i].z + sc[i].w;
        }
        s0 += __shfl_xor_sync(0xffffffffu, s0, 1);
        s0 += __shfl_xor_sync(0xffffffffu, s0, 2);
        s1 += __shfl_xor_sync(0xffffffffu, s1, 1);
        s1 += __shfl_xor_sync(0xffffffffu, s1, 2);
        float inv0 = 1.0f / s0, inv1 = 1.0f / s1;

        float4 o[4];
        #pragma unroll
        for (int i = 0; i < 4; i++) o[i] = make_float4(0.f, 0.f, 0.f, 0.f);
        #pragma unroll
        for (int tk = 0; tk < 16; tk++) {
            uint32_t Ahi[4], Alo[4];
            split2(sc[2 * tk].x,     sc[2 * tk].y,     Ahi[0], Alo[0]);
            split2(sc[2 * tk].z,     sc[2 * tk].w,     Ahi[1], Alo[1]);
            split2(sc[2 * tk + 1].x, sc[2 * tk + 1].y, Ahi[2], Alo[2]);
            split2(sc[2 * tk + 1].z, sc[2 * tk + 1].w, Ahi[3], Alo[3]);
            uint32_t off = (uint32_t)((tk * 16 + lrowT) * 80) + lcolT2;
            uint32_t vh0[4], vh1[4], vl0[4], vl1[4];
            ldsm4t(vh0, sb + AS_VHI + off); ldsm4t(vh1, sb + AS_VHI + off + 32);
            ldsm4t(vl0, sb + AS_VLO + off); ldsm4t(vl1, sb + AS_VLO + off + 32);
            mma16816(o[0], Ahi, vh0[0], vh0[1]); mma16816(o[1], Ahi, vh0[2], vh0[3]);
            mma16816(o[2], Ahi, vh1[0], vh1[1]); mma16816(o[3], Ahi, vh1[2], vh1[3]);
            mma16816(o[0], Alo, vh0[0], vh0[1]); mma16816(o[1], Alo, vh0[2], vh0[3]);
            mma16816(o[2], Alo, vh1[0], vh1[1]); mma16816(o[3], Alo, vh1[2], vh1[3]);
            mma16816(o[0], Ahi, vl0[0], vl0[1]); mma16816(o[1], Ahi, vl0[2], vl0[3]);
            mma16816(o[2], Ahi, vl1[0], vl1[1]); mma16816(o[3], Ahi, vl1[2], vl1[3]);
        }

        const float* vmean = (const float*)(sm + AS_VMEAN);
        size_t ob = ((size_t)b * 256 + tok0) * 256 + h * 32;
        #pragma unroll
        for (int dt = 0; dt < 4; dt++) {
            int d = dt * 8 + cc;
            float vm0 = vmean[d], vm1 = vmean[d + 1];
            uint32_t hi, lo;
            split2(o[dt].x * inv0 + vm0, o[dt].y * inv0 + vm1, hi, lo);
            *(uint32_t*)&g_ath[ob + d] = hi;
            *(uint32_t*)&g_atl[ob + d] = lo;
            split2(o[dt].z * inv1 + vm0, o[dt].w * inv1 + vm1, hi, lo);
            *(uint32_t*)&g_ath[ob + 8 * 256 + d] = hi;
            *(uint32_t*)&g_atl[ob + 8 * 256 + d] = lo;
        }
    }
}

// ---------------- launch -----------------------------------------------------
extern "C" void kernel_launch(void* const* d_in, const int* in_sizes, int n_in,
                              void* d_out, int out_size) {
    const float* x             = (const float*)d_in[0];
    const float* qkv_w         = (const float*)d_in[1];
    const float* qkv_b         = (const float*)d_in[2];
    const float* proj_w        = (const float*)d_in[3];
    const float* proj_b        = (const float*)d_in[4];
    const float* logit_scale   = (const float*)d_in[5];
    const float* val_res_scale = (const float*)d_in[6];
    const float* mlp1_w        = (const float*)d_in[7];
    const float* mlp1_b        = (const float*)d_in[8];
    const float* mlp2_w        = (const float*)d_in[9];
    const float* bias_scale    = (const float*)d_in[10];
    float* out = (float*)d_out;

    cudaFuncSetAttribute(attn_mma_kernel, cudaFuncAttributeMaxDynamicSharedMemorySize,
                         ATTN_SMEM_BYTES);
    cudaFuncSetAttribute(gemm_mma_kernel<true>, cudaFuncAttributeMaxDynamicSharedMemorySize,
                         GEMM_SMEM_BYTES);
    cudaFuncSetAttribute(gemm_mma_kernel<false>, cudaFuncAttributeMaxDynamicSharedMemorySize,
                         GEMM_SMEM_BYTES);

    prep_x_kernel<<<32768, 256>>>(x);
    prep_w_kernel<<<1024, 256>>>(qkv_w, proj_w);
    bias_mlp_kernel<<<256, 128>>>(mlp1_w, mlp1_b, mlp2_w, bias_scale);
    gemm_mma_kernel<true><<<dim3(6, 1024), 256, GEMM_SMEM_BYTES>>>(
        qkv_b, logit_scale, nullptr);
    attn_mma_kernel<<<4096, 256, ATTN_SMEM_BYTES>>>(val_res_scale);
    gemm_mma_kernel<false><<<dim3(2, 1024), 256, GEMM_SMEM_BYTES>>>(
        proj_b, nullptr, out);
}

// round 12
// speedup vs baseline: 1.1383x; 1.1383x over previous
#include <cuda_runtime.h>
#include <cuda_bf16.h>
#include <math.h>
#include <stdint.h>

#define BDIM 512
#define NTOK 256
#define HNUM 8
#define HD   32

// ---------------- scratch (device globals; referenced ONLY in device code) --
__device__ __align__(256) __nv_bfloat16 g_qh[BDIM*HNUM*NTOK*HD];
__device__ __align__(256) __nv_bfloat16 g_kh[BDIM*HNUM*NTOK*HD];
__device__ __align__(256) __nv_bfloat16 g_vh[BDIM*HNUM*NTOK*HD];
__device__ __align__(256) __nv_bfloat16 g_vl[BDIM*HNUM*NTOK*HD];
__device__ __align__(256) float g_att[BDIM*NTOK*256];                // 134 MB
__device__ __align__(256) __nv_bfloat16 g_wqkv_hi[768*256];
__device__ __align__(256) __nv_bfloat16 g_wqkv_lo[768*256];
__device__ __align__(256) __nv_bfloat16 g_wp_hi[256*256];
__device__ __align__(256) __nv_bfloat16 g_wp_lo[256*256];
__device__ __align__(256) __nv_bfloat16 g_bqh[HNUM*NTOK*HD];
__device__ __align__(256) __nv_bfloat16 g_bql[HNUM*NTOK*HD];
__device__ __align__(256) __nv_bfloat16 g_bkh[HNUM*NTOK*HD];
__device__ __align__(256) __nv_bfloat16 g_bkl[HNUM*NTOK*HD];

// ---------------- helpers ----------------------------------------------------
__device__ __forceinline__ uint32_t smem_u32(const void* p) {
    uint32_t a;
    asm("{ .reg .u64 t; cvta.to.shared.u64 t, %1; cvt.u32.u64 %0, t; }" : "=r"(a) : "l"(p));
    return a;
}
__device__ __forceinline__ uint32_t packbf(float x, float y) {
    uint32_t r;
    asm("cvt.rn.bf16x2.f32 %0, %1, %2;" : "=r"(r) : "f"(y), "f"(x));
    return r;
}
__device__ __forceinline__ void split2(float x, float y, uint32_t& hi, uint32_t& lo) {
    hi = packbf(x, y);
    float hx = __uint_as_float(hi << 16);
    float hy = __uint_as_float(hi & 0xffff0000u);
    lo = packbf(x - hx, y - hy);
}
__device__ __forceinline__ void ldsm4(uint32_t (&r)[4], uint32_t a) {
    asm volatile("ldmatrix.sync.aligned.m8n8.x4.shared.b16 {%0,%1,%2,%3}, [%4];"
        : "=r"(r[0]), "=r"(r[1]), "=r"(r[2]), "=r"(r[3]) : "r"(a));
}
__device__ __forceinline__ void ldsm4t(uint32_t (&r)[4], uint32_t a) {
    asm volatile("ldmatrix.sync.aligned.m8n8.x4.trans.shared.b16 {%0,%1,%2,%3}, [%4];"
        : "=r"(r[0]), "=r"(r[1]), "=r"(r[2]), "=r"(r[3]) : "r"(a));
}
__device__ __forceinline__ void mma16816(float4& c, const uint32_t (&a)[4],
                                         uint32_t b0, uint32_t b1) {
    asm volatile("mma.sync.aligned.m16n8k16.row.col.f32.bf16.bf16.f32 "
        "{%0,%1,%2,%3}, {%4,%5,%6,%7}, {%8,%9}, {%0,%1,%2,%3};"
        : "+f"(c.x), "+f"(c.y), "+f"(c.z), "+f"(c.w)
        : "r"(a[0]), "r"(a[1]), "r"(a[2]), "r"(a[3]), "r"(b0), "r"(b1));
}
__device__ __forceinline__ void cpasync16(uint32_t dst, const void* src) {
    asm volatile("cp.async.cg.shared.global [%0], [%1], 16;" :: "r"(dst), "l"(src));
}
#define CP_COMMIT() asm volatile("cp.async.commit_group;" ::: "memory")
#define CP_WAIT(n)  asm volatile("cp.async.wait_group %0;" :: "n"(n) : "memory")

// ---------------- kernel 0: weight transpose + bf16 split -------------------
__global__ __launch_bounds__(256) void prep_w_kernel(
    const float* __restrict__ qkv_w, const float* __restrict__ proj_w) {
    int idx = blockIdx.x * 256 + threadIdx.x;
    if (idx < 196608) {
        int n = idx >> 8, k = idx & 255;
        float v = qkv_w[k * 768 + n];
        __nv_bfloat16 h = __float2bfloat16(v);
        g_wqkv_hi[idx] = h;
        g_wqkv_lo[idx] = __float2bfloat16(v - __bfloat162float(h));
    } else {
        int j = idx - 196608;
        int n = j >> 8, k = j & 255;
        float v = proj_w[k * 256 + n];
        __nv_bfloat16 h = __float2bfloat16(v);
        g_wp_hi[j] = h;
        g_wp_lo[j] = __float2bfloat16(v - __bfloat162float(h));
    }
}

// ---------------- kernel 1: MLP -> bq, bk (bf16 hi/lo) ----------------------
__global__ __launch_bounds__(128) void bias_mlp_kernel(
    const float* __restrict__ m1w, const float* __restrict__ m1b,
    const float* __restrict__ m2w, const float* __restrict__ bs) {
    __shared__ float hf[128];
    const int n = blockIdx.x;
    const int t = threadIdx.x;
    const float invden = 1.0f / log1pf(15.0f);
    const float cy = log1pf((float)(n >> 4)) * invden;
    const float cx = log1pf((float)(n & 15)) * invden;
    {
        float z = cy * m1w[t] + cx * m1w[128 + t] + m1b[t];
        hf[t] = 0.5f * z * (1.0f + erff(z * 0.70710678118654752f));
    }
    __syncthreads();
    const float bscale = bs[0];
    for (int c = t; c < 512; c += 128) {
        float acc = 0.0f;
        #pragma unroll 8
        for (int j = 0; j < 128; j++) acc += hf[j] * m2w[j * 512 + c];
        float sig = 1.0f / (1.0f + __expf(-acc));
        int h = c >> 6, s = (c >> 5) & 1, r = c & 31;
        float v = (s == 0) ? bscale * sig : sig;
        __nv_bfloat16 vh = __float2bfloat16(v);
        __nv_bfloat16 vl = __float2bfloat16(v - __bfloat162float(vh));
        int idx = (h * NTOK + n) * 32 + r;
        if (s == 0) { g_bqh[idx] = vh; g_bql[idx] = vl; }
        else        { g_bkh[idx] = vh; g_bkl[idx] = vl; }
    }
}

// ---------------- GEMM via mma.sync, n128 tile, selective B-lo, cp.async ----
// smem per buffer: hi[128][40bf16]=10240 + lo=10240 -> 20480; x2 = 40960
#define GEMM_BUF_BYTES 20480
#define GEMM_SMEM_BYTES (2 * GEMM_BUF_BYTES)

template <bool QKV>
__global__ __launch_bounds__(256, 2) void gemm_mma_kernel(
    const float* __restrict__ Ain, const float* __restrict__ bias,
    const float* __restrict__ ls, float* __restrict__ outp) {
    extern __shared__ char sm[];
    const uint32_t sb = smem_u32(sm);
    const int t = threadIdx.x, w = t >> 5, lane = t & 31;
    const int m0 = blockIdx.y * 128 + w * 16;
    const int c0 = blockIdx.x * 128;
    const int r = lane >> 2, cc = (lane & 3) * 2;
    const int lrow = (lane & 7) + ((lane >> 4) << 3);
    const int lcol2 = (((lane >> 3) & 1) << 3) * 2;

    const float* A = QKV ? Ain : (const float*)g_att;
    const __nv_bfloat16* Bh = QKV ? g_wqkv_hi : g_wp_hi;
    const __nv_bfloat16* Bl = QKV ? g_wqkv_lo : g_wp_lo;
    const bool need_lo = QKV ? (blockIdx.x >= 4) : true;

    float4 acc[16];
    #pragma unroll
    for (int i = 0; i < 16; i++) acc[i] = make_float4(0.f, 0.f, 0.f, 0.f);

    const float* ar0 = A + (size_t)(m0 + r) * 256;
    const float* ar8 = ar0 + 8 * 256;

    const int srow = t >> 1;
    const int half = t & 1;
    const __nv_bfloat16* bhsrc = Bh + (size_t)(c0 + srow) * 256 + half * 16;
    const __nv_bfloat16* blsrc = Bl + (size_t)(c0 + srow) * 256 + half * 16;
    const uint32_t sdst = sb + srow * 80 + half * 32;

    cpasync16(sdst, bhsrc);
    cpasync16(sdst + 16, bhsrc + 8);
    if (need_lo) {
        cpasync16(sdst + 10240, blsrc);
        cpasync16(sdst + 10240 + 16, blsrc + 8);
    }
    CP_COMMIT();

    #pragma unroll
    for (int kc = 0; kc < 8; kc++) {
        if (kc < 7) {
            uint32_t dst = sdst + ((kc + 1) & 1) * GEMM_BUF_BYTES;
            const __nv_bfloat16* srch = bhsrc + (kc + 1) * 32;
            cpasync16(dst, srch);
            cpasync16(dst + 16, srch + 8);
            if (need_lo) {
                const __nv_bfloat16* srcl = blsrc + (kc + 1) * 32;
                cpasync16(dst + 10240, srcl);
                cpasync16(dst + 10240 + 16, srcl + 8);
            }
            CP_COMMIT();
        }
        uint32_t ah[2][4], al[2][4];
        {
            int k0 = kc * 32 + cc;
            float2 v;
            #pragma unroll
            for (int kk = 0; kk < 2; kk++) {
                int o = k0 + kk * 16;
                v = *(const float2*)(ar0 + o);      split2(v.x, v.y, ah[kk][0], al[kk][0]);
                v = *(const float2*)(ar8 + o);      split2(v.x, v.y, ah[kk][1], al[kk][1]);
                v = *(const float2*)(ar0 + o + 8);  split2(v.x, v.y, ah[kk][2], al[kk][2]);
                v = *(const float2*)(ar8 + o + 8);  split2(v.x, v.y, ah[kk][3], al[kk][3]);
            }
        }
        if (kc < 7) CP_WAIT(1); else CP_WAIT(0);
        __syncthreads();

        const uint32_t bufb = sb + (kc & 1) * GEMM_BUF_BYTES;
        #pragma unroll
        for (int n16 = 0; n16 < 8; n16++) {
            uint32_t off = (uint32_t)((n16 * 16 + lrow) * 80) + lcol2;
            uint32_t rh0[4], rh1[4];
            ldsm4(rh0, bufb + off);
            ldsm4(rh1, bufb + off + 32);
            float4& cA = acc[2 * n16];
            float4& cB = acc[2 * n16 + 1];
            mma16816(cA, ah[0], rh0[0], rh0[1]); mma16816(cA, ah[1], rh1[0], rh1[1]);
            mma16816(cA, al[0], rh0[0], rh0[1]); mma16816(cA, al[1], rh1[0], rh1[1]);
            mma16816(cB, ah[0], rh0[2], rh0[3]); mma16816(cB, ah[1], rh1[2], rh1[3]);
            mma16816(cB, al[0], rh0[2], rh0[3]); mma16816(cB, al[1], rh1[2], rh1[3]);
            if (need_lo) {
                uint32_t rl0[4], rl1[4];
                ldsm4(rl0, bufb + 10240 + off);
                ldsm4(rl1, bufb + 10240 + off + 32);
                mma16816(cA, ah[0], rl0[0], rl0[1]); mma16816(cA, ah[1], rl1[0], rl1[1]);
                mma16816(cB, ah[0], rl0[2], rl0[3]); mma16816(cB, ah[1], rl1[2], rl1[3]);
            }
        }
        __syncthreads();
    }

    const int mrow0 = m0 + r;
    if (QKV) {
        const int s = blockIdx.x >> 1;
        __nv_bfloat16* dh = (s == 0) ? g_qh : (s == 1 ? g_kh : g_vh);
        const int bidx = mrow0 >> 8, n0r = mrow0 & 255, n1r = n0r + 8;
        #pragma unroll
        for (int ti = 0; ti < 16; ti++) {
            int c = c0 + ti * 8 + cc;
            float2 bb = *(const float2*)(bias + c);
            int rem = c & 255;
            int h = rem >> 5, d = rem & 31;
            float scv = (s == 0) ? __ldg(ls + h) : 1.0f;
            float v00 = (acc[ti].x + bb.x) * scv, v01 = (acc[ti].y + bb.y) * scv;
            float v10 = (acc[ti].z + bb.x) * scv, v11 = (acc[ti].w + bb.y) * scv;
            size_t i0 = ((size_t)(bidx * 8 + h) * 256 + n0r) * 32 + d;
            size_t i1 = ((size_t)(bidx * 8 + h) * 256 + n1r) * 32 + d;
            if (s == 2) {
                uint32_t hi, lo;
                split2(v00, v01, hi, lo);
                *(uint32_t*)&dh[i0] = hi; *(uint32_t*)&g_vl[i0] = lo;
                split2(v10, v11, hi, lo);
                *(uint32_t*)&dh[i1] = hi; *(uint32_t*)&g_vl[i1] = lo;
            } else {
                *(uint32_t*)&dh[i0] = packbf(v00, v01);
                *(uint32_t*)&dh[i1] = packbf(v10, v11);
            }
        }
    } else {
        #pragma unroll
        for (int ti = 0; ti < 16; ti++) {
            int c = c0 + ti * 8 + cc;
            float2 bb = *(const float2*)(bias + c);
            *(float2*)(outp + (size_t)mrow0 * 256 + c) =
                make_float2(acc[ti].x + bb.x, acc[ti].y + bb.y);
            *(float2*)(outp + (size_t)(mrow0 + 8) * 256 + c) =
                make_float2(acc[ti].z + bb.x, acc[ti].w + bb.y);
        }
    }
}

// ---------------- attention: q hi-only, K hi-only, V hi+lo, bk 3-term -------
#define AS_KHI   0
#define AS_BKH   20480
#define AS_BKL   40960
#define AS_VHI   61440
#define AS_VLO   81920
#define AS_VMEAN 102400
#define AS_RED   102528
#define ATTN_SMEM_BYTES (102528 + 1024 + 512)

__global__ __launch_bounds__(256) void attn_mma_kernel(const float* __restrict__ vrs) {
    extern __shared__ char sm[];
    const uint32_t sb = smem_u32(sm);
    const int bh = blockIdx.x;
    const int b = bh >> 3, h = bh & 7;
    const int t = threadIdx.x, w = t >> 5, lane = t & 31;
    const int r = lane >> 2, cc = (lane & 3) * 2;
    const int lrow = (lane & 7) + ((lane >> 4) << 3);
    const int lcol2 = (((lane >> 3) & 1) << 3) * 2;
    const int lrowT = lane & 15;
    const int lcolT2 = ((lane >> 4) << 3) * 2;

    {
        size_t gk = (size_t)bh * 8192 + (size_t)t * 32;
        size_t gb = (size_t)h * 8192 + (size_t)t * 32;
        #pragma unroll
        for (int u = 0; u < 4; u++) {
            *(uint4*)(sm + AS_KHI + t * 80 + u * 16) = *(const uint4*)(g_kh + gk + u * 8);
            *(uint4*)(sm + AS_VHI + t * 80 + u * 16) = *(const uint4*)(g_vh + gk + u * 8);
            *(uint4*)(sm + AS_VLO + t * 80 + u * 16) = *(const uint4*)(g_vl + gk + u * 8);
            *(uint4*)(sm + AS_BKH + t * 80 + u * 16) = *(const uint4*)(g_bkh + gb + u * 8);
            *(uint4*)(sm + AS_BKL + t * 80 + u * 16) = *(const uint4*)(g_bkl + gb + u * 8);
        }
    }
    __syncthreads();

    {
        int d = t & 31, grp = t >> 5;
        float s = 0.0f;
        for (int n = grp * 32; n < grp * 32 + 32; n++) {
            uint16_t hv = *(const uint16_t*)(sm + AS_VHI + n * 80 + d * 2);
            uint16_t lv = *(const uint16_t*)(sm + AS_VLO + n * 80 + d * 2);
            s += __uint_as_float(((uint32_t)hv) << 16) + __uint_as_float(((uint32_t)lv) << 16);
        }
        ((float*)(sm + AS_RED))[grp * 32 + d] = s;
    }
    __syncthreads();
    if (t < 32) {
        float s = 0.0f;
        #pragma unroll
        for (int g = 0; g < 8; g++) s += ((float*)(sm + AS_RED))[g * 32 + t];
        ((float*)(sm + AS_VMEAN))[t] = s * (1.0f / 256.0f) * __ldg(vrs + h);
    }
    __syncthreads();

    for (int pass = 0; pass < 2; pass++) {
        const int tok0 = pass * 128 + w * 16 + r;
        uint32_t aqh[2][4], abh[2][4], abl[2][4];
        {
            size_t q0 = (size_t)bh * 8192 + (size_t)tok0 * 32;
            size_t b0 = (size_t)h * 8192 + (size_t)tok0 * 32;
            #pragma unroll
            for (int kk = 0; kk < 2; kk++) {
                int o = kk * 16 + cc;
                aqh[kk][0] = *(const uint32_t*)(g_qh + q0 + o);
                aqh[kk][1] = *(const uint32_t*)(g_qh + q0 + 256 + o);
                aqh[kk][2] = *(const uint32_t*)(g_qh + q0 + o + 8);
                aqh[kk][3] = *(const uint32_t*)(g_qh + q0 + 256 + o + 8);
                abh[kk][0] = *(const uint32_t*)(g_bqh + b0 + o);
                abh[kk][1] = *(const uint32_t*)(g_bqh + b0 + 256 + o);
                abh[kk][2] = *(const uint32_t*)(g_bqh + b0 + o + 8);
                abh[kk][3] = *(const uint32_t*)(g_bqh + b0 + 256 + o + 8);
                abl[kk][0] = *(const uint32_t*)(g_bql + b0 + o);
                abl[kk][1] = *(const uint32_t*)(g_bql + b0 + 256 + o);
                abl[kk][2] = *(const uint32_t*)(g_bql + b0 + o + 8);
                abl[kk][3] = *(const uint32_t*)(g_bql + b0 + 256 + o + 8);
            }
        }

        float4 sc[32];
        #pragma unroll
        for (int i = 0; i < 32; i++) sc[i] = make_float4(0.f, 0.f, 0.f, 0.f);
        #pragma unroll
        for (int n16 = 0; n16 < 16; n16++) {
            uint32_t off = (uint32_t)((n16 * 16 + lrow) * 80) + lcol2;
            uint32_t kh0[4], kh1[4];
            uint32_t bh0[4], bh1[4], bl0[4], bl1[4];
            ldsm4(kh0, sb + AS_KHI + off); ldsm4(kh1, sb + AS_KHI + off + 32);
            ldsm4(bh0, sb + AS_BKH + off); ldsm4(bh1, sb + AS_BKH + off + 32);
            ldsm4(bl0, sb + AS_BKL + off); ldsm4(bl1, sb + AS_BKL + off + 32);
            float4& cA = sc[2 * n16];
            float4& cB = sc[2 * n16 + 1];
            mma16816(cA, aqh[0], kh0[0], kh0[1]); mma16816(cA, aqh[1], kh1[0], kh1[1]);
            mma16816(cA, abh[0], bh0[0], bh0[1]); mma16816(cA, abh[1], bh1[0], bh1[1]);
            mma16816(cA, abl[0], bh0[0], bh0[1]); mma16816(cA, abl[1], bh1[0], bh1[1]);
            mma16816(cA, abh[0], bl0[0], bl0[1]); mma16816(cA, abh[1], bl1[0], bl1[1]);
            mma16816(cB, aqh[0], kh0[2], kh0[3]); mma16816(cB, aqh[1], kh1[2], kh1[3]);
            mma16816(cB, abh[0], bh0[2], bh0[3]); mma16816(cB, abh[1], bh1[2], bh1[3]);
            mma16816(cB, abl[0], bh0[2], bh0[3]); mma16816(cB, abl[1], bh1[2], bh1[3]);
            mma16816(cB, abh[0], bl0[2], bl0[3]); mma16816(cB, abh[1], bl1[2], bl1[3]);
        }

        float m0 = -1e30f, m1 = -1e30f;
        #pragma unroll
        for (int i = 0; i < 32; i++) {
            m0 = fmaxf(m0, fmaxf(sc[i].x, sc[i].y));
            m1 = fmaxf(m1, fmaxf(sc[i].z, sc[i].w));
        }
        m0 = fmaxf(m0, __shfl_xor_sync(0xffffffffu, m0, 1));
        m0 = fmaxf(m0, __shfl_xor_sync(0xffffffffu, m0, 2));
        m1 = fmaxf(m1, __shfl_xor_sync(0xffffffffu, m1, 1));
        m1 = fmaxf(m1, __shfl_xor_sync(0xffffffffu, m1, 2));
        float s0 = 0.f, s1 = 0.f;
        #pragma unroll
        for (int i = 0; i < 32; i++) {
            sc[i].x = __expf(sc[i].x - m0); sc[i].y = __expf(sc[i].y - m0);
            sc[i].z = __expf(sc[i].z - m1); sc[i].w = __expf(sc[i].w - m1);
            s0 += sc[i].x + sc[i].y; s1 += sc[i].z + sc[i].w;
        }
        s0 += __shfl_xor_sync(0xffffffffu, s0, 1);
        s0 += __shfl_xor_sync(0xffffffffu, s0, 2);
        s1 += __shfl_xor_sync(0xffffffffu, s1, 1);
        s1 += __shfl_xor_sync(0xffffffffu, s1, 2);
        float inv0 = 1.0f / s0, inv1 = 1.0f / s1;

        float4 o[4];
        #pragma unroll
        for (int i = 0; i < 4; i++) o[i] = make_float4(0.f, 0.f, 0.f, 0.f);
        #pragma unroll
        for (int tk = 0; tk < 16; tk++) {
            uint32_t Ahi[4], Alo[4];
            split2(sc[2 * tk].x,     sc[2 * tk].y,     Ahi[0], Alo[0]);
            split2(sc[2 * tk].z,     sc[2 * tk].w,     Ahi[1], Alo[1]);
            split2(sc[2 * tk + 1].x, sc[2 * tk + 1].y, Ahi[2], Alo[2]);
            split2(sc[2 * tk + 1].z, sc[2 * tk + 1].w, Ahi[3], Alo[3]);
            uint32_t off = (uint32_t)((tk * 16 + lrowT) * 80) + lcolT2;
            uint32_t vh0[4], vh1[4], vl0[4], vl1[4];
            ldsm4t(vh0, sb + AS_VHI + off); ldsm4t(vh1, sb + AS_VHI + off + 32);
            ldsm4t(vl0, sb + AS_VLO + off); ldsm4t(vl1, sb + AS_VLO + off + 32);
            mma16816(o[0], Ahi, vh0[0], vh0[1]); mma16816(o[1], Ahi, vh0[2], vh0[3]);
            mma16816(o[2], Ahi, vh1[0], vh1[1]); mma16816(o[3], Ahi, vh1[2], vh1[3]);
            mma16816(o[0], Alo, vh0[0], vh0[1]); mma16816(o[1], Alo, vh0[2], vh0[3]);
            mma16816(o[2], Alo, vh1[0], vh1[1]); mma16816(o[3], Alo, vh1[2], vh1[3]);
            mma16816(o[0], Ahi, vl0[0], vl0[1]); mma16816(o[1], Ahi, vl0[2], vl0[3]);
            mma16816(o[2], Ahi, vl1[0], vl1[1]); mma16816(o[3], Ahi, vl1[2], vl1[3]);
        }

        const float* vmean = (const float*)(sm + AS_VMEAN);
        float* out0 = g_att + ((size_t)b * 256 + tok0) * 256 + h * 32;
        float* out1 = out0 + 8 * 256;
        #pragma unroll
        for (int dt = 0; dt < 4; dt++) {
            int d = dt * 8 + cc;
            float vm0 = vmean[d], vm1 = vmean[d + 1];
            *(float2*)(out0 + d) = make_float2(o[dt].x * inv0 + vm0, o[dt].y * inv0 + vm1);
            *(float2*)(out1 + d) = make_float2(o[dt].z * inv1 + vm0, o[dt].w * inv1 + vm1);
        }
    }
}

// ---------------- launch -----------------------------------------------------
extern "C" void kernel_launch(void* const* d_in, const int* in_sizes, int n_in,
                              void* d_out, int out_size) {
    const float* x             = (const float*)d_in[0];
    const float* qkv_w         = (const float*)d_in[1];
    const float* qkv_b         = (const float*)d_in[2];
    const float* proj_w        = (const float*)d_in[3];
    const float* proj_b        = (const float*)d_in[4];
    const float* logit_scale   = (const float*)d_in[5];
    const float* val_res_scale = (const float*)d_in[6];
    const float* mlp1_w        = (const float*)d_in[7];
    const float* mlp1_b        = (const float*)d_in[8];
    const float* mlp2_w        = (const float*)d_in[9];
    const float* bias_scale    = (const float*)d_in[10];
    float* out = (float*)d_out;

    cudaFuncSetAttribute(attn_mma_kernel, cudaFuncAttributeMaxDynamicSharedMemorySize,
                         ATTN_SMEM_BYTES);
    cudaFuncSetAttribute(gemm_mma_kernel<true>, cudaFuncAttributeMaxDynamicSharedMemorySize,
                         GEMM_SMEM_BYTES);
    cudaFuncSetAttribute(gemm_mma_kernel<false>, cudaFuncAttributeMaxDynamicSharedMemorySize,
                         GEMM_SMEM_BYTES);

    prep_w_kernel<<<1024, 256>>>(qkv_w, proj_w);
    bias_mlp_kernel<<<256, 128>>>(mlp1_w, mlp1_b, mlp2_w, bias_scale);
    gemm_mma_kernel<true><<<dim3(6, 1024), 256, GEMM_SMEM_BYTES>>>(
        x, qkv_b, logit_scale, nullptr);
    attn_mma_kernel<<<4096, 256, ATTN_SMEM_BYTES>>>(val_res_scale);
    gemm_mma_kernel<false><<<dim3(2, 1024), 256, GEMM_SMEM_BYTES>>>(
        x /*unused*/, proj_b, nullptr, out);
}